// round 2
// baseline (speedup 1.0000x reference)
#include <cuda_runtime.h>
#include <cstddef>

// ---------------- constants ----------------
#define NWIN   2048          // number of windows (B_)
#define NTOK   64            // tokens per window (8x8)
#define CDIM   128
#define NHEAD  4
#define HDIM   32
#define IMGH   256
#define IMGW   256
#define NB     2             // image batch

// ---------------- scratch (device globals; no allocs allowed) ----------------
__device__ float g_qn [NWIN*NHEAD*NTOK*HDIM];
__device__ float g_kn [NWIN*NHEAD*NTOK*HDIM];
__device__ float g_knr[NWIN*NHEAD*NTOK*HDIM];
__device__ float g_v  [NWIN*NHEAD*NTOK*HDIM];
__device__ float g_imgA[(size_t)NB*IMGH*IMGW*CDIM];
__device__ float g_imgB[(size_t)NB*IMGH*IMGW*CDIM];
__device__ float g_imgC[(size_t)NB*IMGH*IMGW*CDIM];
__device__ float g_wt_qkv[128*384];   // [k][o]
__device__ float g_wt_proj[128*128];  // [k][o]

// ---------------- weight transpose ----------------
__global__ void transpose_weights(const float* __restrict__ qkv_w,
                                  const float* __restrict__ proj_w) {
    int t = blockIdx.x * blockDim.x + threadIdx.x;   // 0..49151
    if (t < 384*128) { int o = t / 128, k = t % 128; g_wt_qkv[k*384 + o] = qkv_w[t]; }
    if (t < 128*128) { int o = t / 128, k = t % 128; g_wt_proj[k*128 + o] = proj_w[t]; }
}

#define FMA_ROW(r, a) \
    acc[r][0] += (a)*b0.x; acc[r][1] += (a)*b0.y; acc[r][2] += (a)*b0.z; acc[r][3] += (a)*b0.w; \
    acc[r][4] += (a)*b1.x; acc[r][5] += (a)*b1.y; acc[r][6] += (a)*b1.z; acc[r][7] += (a)*b1.w;

// ---------------- QKV GEMM + optional per-head normalize ----------------
// src tokens (NWIN,64,128) -> dst (NWIN,NHEAD,64,32)
__global__ __launch_bounds__(256) void qkv_kernel(
    const float* __restrict__ src, const float* __restrict__ qkv_b,
    float* __restrict__ dst, int which, int do_norm)
{
    __shared__ float smem[64*129 + 256];   // union: [sA 32x65 | sB 32x128] then [S 64x129 | rn 256]
    float* sA = smem;
    float* sB = smem + 32*65;

    const int t   = threadIdx.x;
    const int win = blockIdx.x;
    const int ty  = t >> 4, tx = t & 15;
    const int ty4 = ty*4,  tx8 = tx*8;

    float acc[4][8];
    #pragma unroll
    for (int i = 0; i < 4; i++)
        #pragma unroll
        for (int j = 0; j < 8; j++) acc[i][j] = 0.f;

    const float* srcw = src + (size_t)win * NTOK * CDIM;

    for (int kc = 0; kc < 128; kc += 32) {
        #pragma unroll
        for (int i = 0; i < 2; i++) {            // A: 64 tok x 32 ch
            int s = t + i*256;
            int tok = s >> 3, f4 = s & 7;
            float4 v = *(const float4*)(srcw + tok*CDIM + kc + f4*4);
            sA[(f4*4+0)*65 + tok] = v.x;
            sA[(f4*4+1)*65 + tok] = v.y;
            sA[(f4*4+2)*65 + tok] = v.z;
            sA[(f4*4+3)*65 + tok] = v.w;
        }
        #pragma unroll
        for (int i = 0; i < 4; i++) {            // B: 32 x 128
            int s = t + i*256;
            int kk = s >> 5, cg = s & 31;
            *(float4*)(sB + kk*128 + cg*4) =
                *(const float4*)(g_wt_qkv + (kc+kk)*384 + which*128 + cg*4);
        }
        __syncthreads();
        #pragma unroll
        for (int kk = 0; kk < 32; kk++) {
            float a0 = sA[kk*65 + ty4 + 0];
            float a1 = sA[kk*65 + ty4 + 1];
            float a2 = sA[kk*65 + ty4 + 2];
            float a3 = sA[kk*65 + ty4 + 3];
            float4 b0 = *(const float4*)(sB + kk*128 + tx8);
            float4 b1 = *(const float4*)(sB + kk*128 + tx8 + 4);
            FMA_ROW(0, a0) FMA_ROW(1, a1) FMA_ROW(2, a2) FMA_ROW(3, a3)
        }
        __syncthreads();
    }

    // epilogue through smem (needed for per-head norms + layout permute)
    float* S  = smem;            // [64][129]
    float* rn = smem + 64*129;   // [256]
    __syncthreads();
    #pragma unroll
    for (int i = 0; i < 4; i++)
        #pragma unroll
        for (int j = 0; j < 8; j++)
            S[(ty4+i)*129 + tx8 + j] = acc[i][j] + qkv_b[which*128 + tx8 + j];
    __syncthreads();

    if (do_norm) {
        int head = t >> 6, tok = t & 63;
        float ssum = 0.f;
        #pragma unroll
        for (int d = 0; d < 32; d++) {
            float v = S[tok*129 + head*32 + d];
            ssum += v*v;
        }
        rn[head*64 + tok] = 1.f / fmaxf(sqrtf(ssum), 1e-12f);
        __syncthreads();
    }

    float* dstw = dst + (size_t)win * NHEAD * NTOK * HDIM;
    #pragma unroll
    for (int i = 0; i < 8; i++) {
        int s4 = t + i*256;
        int o  = s4*4;
        int head = o >> 11;
        int tok  = (o >> 5) & 63;
        int d    = o & 31;
        float sc = do_norm ? rn[head*64 + tok] : 1.f;
        float4 v;
        v.x = S[tok*129 + head*32 + d + 0] * sc;
        v.y = S[tok*129 + head*32 + d + 1] * sc;
        v.z = S[tok*129 + head*32 + d + 2] * sc;
        v.w = S[tok*129 + head*32 + d + 3] * sc;
        *(float4*)(dstw + o) = v;
    }
}

// ---------------- attention (per window, 4 heads) ----------------
// dynamic smem: sq(64x33) sk(64x33) skr/v(64x33) S1(64x65) S2(64x65) bias(900)
#define ATTN_SMEM_FLOATS (2112*3 + 4160*2 + 900)
__global__ __launch_bounds__(256) void attn_kernel(
    const float* __restrict__ rel_bias, const float* __restrict__ logit_scale,
    const float* __restrict__ gating)
{
    extern __shared__ float sm[];
    float* sq    = sm;
    float* sk    = sm + 2112;
    float* skr   = sm + 4224;     // later reused for V
    float* S1    = sm + 6336;
    float* S2    = sm + 6336 + 4160;
    float* sbias = sm + 6336 + 8320;

    const int t   = threadIdx.x;
    const int win = blockIdx.x;
    const int b   = win >> 10;
    const int hw  = (win & 1023) >> 5;
    const int ww  = win & 31;

    for (int i = t; i < 225*4; i += 256) sbias[i] = rel_bias[i];

    for (int head = 0; head < 4; head++) {
        float ls = __expf(fminf(logit_scale[head], 4.6051702f));   // log(100)
        float gt = 1.f / (1.f + __expf(-gating[head]));
        const size_t base = ((size_t)(win*4 + head)) * (NTOK*HDIM);

        #pragma unroll
        for (int i = 0; i < 2; i++) {
            int s = t + i*256;
            int tok = s >> 3, f4 = s & 7;
            float4 vq = *(const float4*)(g_qn  + base + tok*32 + f4*4);
            float4 vk = *(const float4*)(g_kn  + base + tok*32 + f4*4);
            float4 vr = *(const float4*)(g_knr + base + tok*32 + f4*4);
            int o = tok*33 + f4*4;
            sq[o+0]=vq.x; sq[o+1]=vq.y; sq[o+2]=vq.z; sq[o+3]=vq.w;
            sk[o+0]=vk.x; sk[o+1]=vk.y; sk[o+2]=vk.z; sk[o+3]=vk.w;
            skr[o+0]=vr.x; skr[o+1]=vr.y; skr[o+2]=vr.z; skr[o+3]=vr.w;
        }
        __syncthreads();

        // scores: thread computes 4x4 of both S1 and S2
        const int tn = t >> 4, tm = t & 15;
        float a1[4][4], a2[4][4];
        #pragma unroll
        for (int i=0;i<4;i++)
            #pragma unroll
            for (int j=0;j<4;j++) { a1[i][j]=0.f; a2[i][j]=0.f; }
        for (int d = 0; d < 32; d++) {
            float q0 = sq[(tn*4+0)*33 + d];
            float q1 = sq[(tn*4+1)*33 + d];
            float q2 = sq[(tn*4+2)*33 + d];
            float q3 = sq[(tn*4+3)*33 + d];
            #pragma unroll
            for (int j = 0; j < 4; j++) {
                float kv = sk [(tm*4+j)*33 + d];
                float rv = skr[(tm*4+j)*33 + d];
                a1[0][j] += q0*kv; a1[1][j] += q1*kv; a1[2][j] += q2*kv; a1[3][j] += q3*kv;
                a2[0][j] += q0*rv; a2[1][j] += q1*rv; a2[2][j] += q2*rv; a2[3][j] += q3*rv;
            }
        }
        #pragma unroll
        for (int i = 0; i < 4; i++)
            #pragma unroll
            for (int j = 0; j < 4; j++) {
                int n = tn*4 + i, m = tm*4 + j;
                int ridx = ((n>>3) - (m>>3) + 7)*15 + ((n&7) - (m&7) + 7);
                float bs = sbias[ridx*4 + head];
                S1[n*65 + m] = a1[i][j]*ls + bs;
                S2[n*65 + m] = a2[i][j]*ls + bs;
            }
        __syncthreads();

        // softmax: one thread per row (rows 0-63 -> S1, 64-127 -> S2)
        if (t < 128) {
            float* Sx = (t < 64) ? S1 : S2;
            int r = t & 63;
            float mx = Sx[r*65];
            for (int m = 1; m < 64; m++) mx = fmaxf(mx, Sx[r*65 + m]);
            float sum = 0.f;
            for (int m = 0; m < 64; m++) {
                float e = __expf(Sx[r*65 + m] - mx);
                Sx[r*65 + m] = e; sum += e;
            }
            float inv = 1.f / sum;
            for (int m = 0; m < 64; m++) Sx[r*65 + m] *= inv;
        }
        __syncthreads();

        // gated combine into S1, and load V into skr
        #pragma unroll
        for (int u = 0; u < 16; u++) {
            int e = t*16 + u;
            int n = e >> 6, m = e & 63;
            S1[n*65 + m] = (1.f - gt)*S1[n*65 + m] + gt*S2[n*65 + m];
        }
        #pragma unroll
        for (int i = 0; i < 2; i++) {
            int s = t + i*256;
            int tok = s >> 3, f4 = s & 7;
            float4 vv = *(const float4*)(g_v + base + tok*32 + f4*4);
            int o = tok*33 + f4*4;
            skr[o+0]=vv.x; skr[o+1]=vv.y; skr[o+2]=vv.z; skr[o+3]=vv.w;
        }
        __syncthreads();

        // AV: thread -> (token n, 8 head-dims), write straight to image layout
        {
            int n  = t >> 2;
            int d0 = (t & 3) * 8;
            float o[8];
            #pragma unroll
            for (int j = 0; j < 8; j++) o[j] = 0.f;
            for (int m = 0; m < 64; m++) {
                float a = S1[n*65 + m];
                #pragma unroll
                for (int j = 0; j < 8; j++) o[j] += a * skr[m*33 + d0 + j];
            }
            int i1 = n >> 3, j1 = n & 7;
            size_t pix = (((size_t)b*IMGH + hw*8 + i1)*IMGW + (ww*8 + j1)) * CDIM;
            *(float4*)(g_imgA + pix + head*32 + d0)     = make_float4(o[0],o[1],o[2],o[3]);
            *(float4*)(g_imgA + pix + head*32 + d0 + 4) = make_float4(o[4],o[5],o[6],o[7]);
        }
        __syncthreads();
    }
}

// ---------------- conv3x3 (SAME), fused bias / relu / residual ----------------
// in/out selected by id: 0=g_imgA, 1=g_imgB, 2=g_imgC  (avoids host symbol lookup)
__device__ __forceinline__ float* img_by_id(int id) {
    return id == 0 ? g_imgA : (id == 1 ? g_imgB : g_imgC);
}

__global__ __launch_bounds__(256) void conv3x3_kernel(
    int in_id, const float* __restrict__ w,
    const float* __restrict__ bias, int res_id,   // res_id < 0 -> no residual
    int out_id, int relu)
{
    __shared__ float sA[32*65];
    __shared__ float sB[32*128];

    const float* in  = img_by_id(in_id);
    float*       out = img_by_id(out_id);
    const float* res = (res_id >= 0) ? img_by_id(res_id) : nullptr;

    const int t   = threadIdx.x;
    const int blk = blockIdx.x;
    const int b   = blk >> 10;
    const int th  = (blk & 1023) >> 5;
    const int tw  = blk & 31;
    const int h0  = th*8, w0 = tw*8;
    const int ty  = t >> 4, tx = t & 15;
    const int ty4 = ty*4,  tx8 = tx*8;

    float acc[4][8];
    #pragma unroll
    for (int i = 0; i < 4; i++)
        #pragma unroll
        for (int j = 0; j < 8; j++) acc[i][j] = 0.f;

    for (int tap = 0; tap < 9; tap++) {
        const int dy = tap/3 - 1, dx = tap%3 - 1;
        for (int kc = 0; kc < 128; kc += 32) {
            #pragma unroll
            for (int i = 0; i < 2; i++) {
                int s = t + i*256;
                int p = s >> 3, f4 = s & 7;
                int hh = h0 + (p >> 3) + dy;
                int wp = w0 + (p & 7) + dx;
                float4 v = make_float4(0.f,0.f,0.f,0.f);
                if (hh >= 0 && hh < IMGH && wp >= 0 && wp < IMGW)
                    v = *(const float4*)(in + (((size_t)b*IMGH + hh)*IMGW + wp)*CDIM + kc + f4*4);
                sA[(f4*4+0)*65 + p] = v.x;
                sA[(f4*4+1)*65 + p] = v.y;
                sA[(f4*4+2)*65 + p] = v.z;
                sA[(f4*4+3)*65 + p] = v.w;
            }
            #pragma unroll
            for (int i = 0; i < 4; i++) {
                int s = t + i*256;
                int kk = s >> 5, cg = s & 31;
                *(float4*)(sB + kk*128 + cg*4) =
                    *(const float4*)(w + ((size_t)(tap*128) + (kc+kk))*128 + cg*4);
            }
            __syncthreads();
            #pragma unroll
            for (int kk = 0; kk < 32; kk++) {
                float a0 = sA[kk*65 + ty4 + 0];
                float a1 = sA[kk*65 + ty4 + 1];
                float a2 = sA[kk*65 + ty4 + 2];
                float a3 = sA[kk*65 + ty4 + 3];
                float4 b0 = *(const float4*)(sB + kk*128 + tx8);
                float4 b1 = *(const float4*)(sB + kk*128 + tx8 + 4);
                FMA_ROW(0, a0) FMA_ROW(1, a1) FMA_ROW(2, a2) FMA_ROW(3, a3)
            }
            __syncthreads();
        }
    }

    float bs[8];
    #pragma unroll
    for (int j = 0; j < 8; j++) bs[j] = bias[tx8 + j];

    #pragma unroll
    for (int i = 0; i < 4; i++) {
        int p = ty4 + i;
        size_t pbase = (((size_t)b*IMGH + h0 + (p >> 3))*IMGW + w0 + (p & 7))*CDIM + tx8;
        float v[8];
        #pragma unroll
        for (int j = 0; j < 8; j++) {
            v[j] = acc[i][j] + bs[j];
            if (relu) v[j] = fmaxf(v[j], 0.f);
        }
        if (res) {
            float4 r0 = *(const float4*)(res + pbase);
            float4 r1 = *(const float4*)(res + pbase + 4);
            v[0]+=r0.x; v[1]+=r0.y; v[2]+=r0.z; v[3]+=r0.w;
            v[4]+=r1.x; v[5]+=r1.y; v[6]+=r1.z; v[7]+=r1.w;
        }
        *(float4*)(out + pbase)     = make_float4(v[0],v[1],v[2],v[3]);
        *(float4*)(out + pbase + 4) = make_float4(v[4],v[5],v[6],v[7]);
    }
}

// ---------------- proj 1x1 + window_partition -> d_out ----------------
__global__ __launch_bounds__(256) void proj_kernel(
    const float* __restrict__ proj_b, float* __restrict__ out)
{
    __shared__ float sA[32*65];
    __shared__ float sB[32*128];

    const float* img = g_imgA;

    const int t   = threadIdx.x;
    const int win = blockIdx.x;
    const int b   = win >> 10;
    const int hw  = (win & 1023) >> 5;
    const int ww  = win & 31;
    const int ty  = t >> 4, tx = t & 15;
    const int ty4 = ty*4,  tx8 = tx*8;

    float acc[4][8];
    #pragma unroll
    for (int i = 0; i < 4; i++)
        #pragma unroll
        for (int j = 0; j < 8; j++) acc[i][j] = 0.f;

    for (int kc = 0; kc < 128; kc += 32) {
        #pragma unroll
        for (int i = 0; i < 2; i++) {
            int s = t + i*256;
            int tok = s >> 3, f4 = s & 7;
            int i1 = tok >> 3, j1 = tok & 7;
            size_t pix = (((size_t)b*IMGH + hw*8 + i1)*IMGW + (ww*8 + j1))*CDIM;
            float4 v = *(const float4*)(img + pix + kc + f4*4);
            sA[(f4*4+0)*65 + tok] = v.x;
            sA[(f4*4+1)*65 + tok] = v.y;
            sA[(f4*4+2)*65 + tok] = v.z;
            sA[(f4*4+3)*65 + tok] = v.w;
        }
        #pragma unroll
        for (int i = 0; i < 4; i++) {
            int s = t + i*256;
            int kk = s >> 5, cg = s & 31;
            *(float4*)(sB + kk*128 + cg*4) =
                *(const float4*)(g_wt_proj + (kc+kk)*128 + cg*4);
        }
        __syncthreads();
        #pragma unroll
        for (int kk = 0; kk < 32; kk++) {
            float a0 = sA[kk*65 + ty4 + 0];
            float a1 = sA[kk*65 + ty4 + 1];
            float a2 = sA[kk*65 + ty4 + 2];
            float a3 = sA[kk*65 + ty4 + 3];
            float4 b0 = *(const float4*)(sB + kk*128 + tx8);
            float4 b1 = *(const float4*)(sB + kk*128 + tx8 + 4);
            FMA_ROW(0, a0) FMA_ROW(1, a1) FMA_ROW(2, a2) FMA_ROW(3, a3)
        }
        __syncthreads();
    }

    #pragma unroll
    for (int i = 0; i < 4; i++) {
        int tok = ty4 + i;
        size_t obase = ((size_t)win*NTOK + tok)*CDIM + tx8;
        float4 v0, v1;
        v0.x = acc[i][0] + proj_b[tx8+0]; v0.y = acc[i][1] + proj_b[tx8+1];
        v0.z = acc[i][2] + proj_b[tx8+2]; v0.w = acc[i][3] + proj_b[tx8+3];
        v1.x = acc[i][4] + proj_b[tx8+4]; v1.y = acc[i][5] + proj_b[tx8+5];
        v1.z = acc[i][6] + proj_b[tx8+6]; v1.w = acc[i][7] + proj_b[tx8+7];
        *(float4*)(out + obase)     = v0;
        *(float4*)(out + obase + 4) = v1;
    }
}

// ---------------- qkv dst selector wrappers ----------------
__global__ __launch_bounds__(256) void qkv_launcher() {}  // unused placeholder

// ---------------- launch ----------------
extern "C" void kernel_launch(void* const* d_in, const int* in_sizes, int n_in,
                              void* d_out, int out_size) {
    const float* x         = (const float*)d_in[0];
    const float* ref       = (const float*)d_in[1];
    const float* qkv_w     = (const float*)d_in[2];
    const float* qkv_b     = (const float*)d_in[3];
    const float* proj_w    = (const float*)d_in[4];
    const float* proj_b    = (const float*)d_in[5];
    const float* t11w      = (const float*)d_in[6];
    const float* t11b      = (const float*)d_in[7];
    const float* t12w      = (const float*)d_in[8];
    const float* t12b      = (const float*)d_in[9];
    const float* t21w      = (const float*)d_in[10];
    const float* t21b      = (const float*)d_in[11];
    const float* t22w      = (const float*)d_in[12];
    const float* t22b      = (const float*)d_in[13];
    const float* rel_bias  = (const float*)d_in[14];
    const float* logit_sc  = (const float*)d_in[15];
    const float* gating    = (const float*)d_in[16];
    float* out = (float*)d_out;

    // device scratch pointers via symbol lookup is avoided for img buffers;
    // qkv outputs still need host-side pointers -> use cudaGetSymbolAddress once per call
    float *qn, *kn, *knr, *v;
    cudaGetSymbolAddress((void**)&qn,  g_qn);
    cudaGetSymbolAddress((void**)&kn,  g_kn);
    cudaGetSymbolAddress((void**)&knr, g_knr);
    cudaGetSymbolAddress((void**)&v,   g_v);

    cudaFuncSetAttribute(attn_kernel, cudaFuncAttributeMaxDynamicSharedMemorySize,
                         ATTN_SMEM_FLOATS * (int)sizeof(float));

    transpose_weights<<<192, 256>>>(qkv_w, proj_w);

    qkv_kernel<<<NWIN, 256>>>(x,   qkv_b, qn,  0, 1);
    qkv_kernel<<<NWIN, 256>>>(x,   qkv_b, kn,  1, 1);
    qkv_kernel<<<NWIN, 256>>>(x,   qkv_b, v,   2, 0);
    qkv_kernel<<<NWIN, 256>>>(ref, qkv_b, knr, 1, 1);

    attn_kernel<<<NWIN, 256, ATTN_SMEM_FLOATS * (int)sizeof(float)>>>(rel_bias, logit_sc, gating);

    // conv chain on device-global images: A -> B -> C(+A) -> B -> A(+C)
    conv3x3_kernel<<<NWIN, 256>>>(0, t11w, t11b, -1, 1, 1);
    conv3x3_kernel<<<NWIN, 256>>>(1, t12w, t12b,  0, 2, 0);
    conv3x3_kernel<<<NWIN, 256>>>(2, t21w, t21b, -1, 1, 1);
    conv3x3_kernel<<<NWIN, 256>>>(1, t22w, t22b,  2, 0, 0);

    proj_kernel<<<NWIN, 256>>>(proj_b, out);
}

// round 3
// speedup vs baseline: 2.6726x; 2.6726x over previous
#include <cuda_runtime.h>
#include <cuda_bf16.h>
#include <cstdint>
#include <cstddef>

// ---------------- constants ----------------
#define NWIN   2048          // number of windows (B_)
#define NTOK   64            // tokens per window (8x8)
#define CDIM   128
#define NHEAD  4
#define HDIM   32
#define IMGH   256
#define IMGW   256
#define NB     2             // image batch
#define KCONV  1152          // 9*128

// ---------------- scratch (device globals; no allocs allowed) ----------------
__device__ float g_qn [NWIN*NHEAD*NTOK*HDIM];
__device__ float g_kn [NWIN*NHEAD*NTOK*HDIM];
__device__ float g_knr[NWIN*NHEAD*NTOK*HDIM];
__device__ float g_v  [NWIN*NHEAD*NTOK*HDIM];
__device__ float g_imgA[(size_t)NB*IMGH*IMGW*CDIM];
__device__ float g_imgB[(size_t)NB*IMGH*IMGW*CDIM];
__device__ float g_imgC[(size_t)NB*IMGH*IMGW*CDIM];
__device__ float g_wt_qkv[128*384];   // [k][o]
__device__ float g_wt_proj[128*128];  // [k][o]
__device__ __nv_bfloat16 g_wbf_hi[4*KCONV*128];  // conv weights split hi [conv][k][o]
__device__ __nv_bfloat16 g_wbf_lo[4*KCONV*128];

// ---------------- weight transpose (qkv/proj fp32) ----------------
__global__ void transpose_weights(const float* __restrict__ qkv_w,
                                  const float* __restrict__ proj_w) {
    int t = blockIdx.x * blockDim.x + threadIdx.x;   // 0..49151
    if (t < 384*128) { int o = t / 128, k = t % 128; g_wt_qkv[k*384 + o] = qkv_w[t]; }
    if (t < 128*128) { int o = t / 128, k = t % 128; g_wt_proj[k*128 + o] = proj_w[t]; }
}

// ---------------- conv weight split to bf16 hi/lo ----------------
__global__ void split_weights(const float* __restrict__ w0, const float* __restrict__ w1,
                              const float* __restrict__ w2, const float* __restrict__ w3) {
    int t = blockIdx.x * blockDim.x + threadIdx.x;   // over 1152*128
    if (t >= KCONV*128) return;
    const float* ws[4] = {w0, w1, w2, w3};
    #pragma unroll
    for (int c = 0; c < 4; c++) {
        float x = ws[c][t];
        __nv_bfloat16 hi = __float2bfloat16(x);
        float lo = x - __bfloat162float(hi);
        g_wbf_hi[c*KCONV*128 + t] = hi;
        g_wbf_lo[c*KCONV*128 + t] = __float2bfloat16(lo);
    }
}

#define FMA_ROW(r, a) \
    acc[r][0] += (a)*b0.x; acc[r][1] += (a)*b0.y; acc[r][2] += (a)*b0.z; acc[r][3] += (a)*b0.w; \
    acc[r][4] += (a)*b1.x; acc[r][5] += (a)*b1.y; acc[r][6] += (a)*b1.z; acc[r][7] += (a)*b1.w;

// ---------------- QKV GEMM + optional per-head normalize ----------------
__global__ __launch_bounds__(256) void qkv_kernel(
    const float* __restrict__ src, const float* __restrict__ qkv_b,
    float* __restrict__ dst, int which, int do_norm)
{
    __shared__ float smem[64*129 + 256];
    float* sA = smem;
    float* sB = smem + 32*65;

    const int t   = threadIdx.x;
    const int win = blockIdx.x;
    const int ty  = t >> 4, tx = t & 15;
    const int ty4 = ty*4,  tx8 = tx*8;

    float acc[4][8];
    #pragma unroll
    for (int i = 0; i < 4; i++)
        #pragma unroll
        for (int j = 0; j < 8; j++) acc[i][j] = 0.f;

    const float* srcw = src + (size_t)win * NTOK * CDIM;

    for (int kc = 0; kc < 128; kc += 32) {
        #pragma unroll
        for (int i = 0; i < 2; i++) {
            int s = t + i*256;
            int tok = s >> 3, f4 = s & 7;
            float4 v = *(const float4*)(srcw + tok*CDIM + kc + f4*4);
            sA[(f4*4+0)*65 + tok] = v.x;
            sA[(f4*4+1)*65 + tok] = v.y;
            sA[(f4*4+2)*65 + tok] = v.z;
            sA[(f4*4+3)*65 + tok] = v.w;
        }
        #pragma unroll
        for (int i = 0; i < 4; i++) {
            int s = t + i*256;
            int kk = s >> 5, cg = s & 31;
            *(float4*)(sB + kk*128 + cg*4) =
                *(const float4*)(g_wt_qkv + (kc+kk)*384 + which*128 + cg*4);
        }
        __syncthreads();
        #pragma unroll
        for (int kk = 0; kk < 32; kk++) {
            float a0 = sA[kk*65 + ty4 + 0];
            float a1 = sA[kk*65 + ty4 + 1];
            float a2 = sA[kk*65 + ty4 + 2];
            float a3 = sA[kk*65 + ty4 + 3];
            float4 b0 = *(const float4*)(sB + kk*128 + tx8);
            float4 b1 = *(const float4*)(sB + kk*128 + tx8 + 4);
            FMA_ROW(0, a0) FMA_ROW(1, a1) FMA_ROW(2, a2) FMA_ROW(3, a3)
        }
        __syncthreads();
    }

    float* S  = smem;            // [64][129]
    float* rn = smem + 64*129;   // [256]
    __syncthreads();
    #pragma unroll
    for (int i = 0; i < 4; i++)
        #pragma unroll
        for (int j = 0; j < 8; j++)
            S[(ty4+i)*129 + tx8 + j] = acc[i][j] + qkv_b[which*128 + tx8 + j];
    __syncthreads();

    if (do_norm) {
        int head = t >> 6, tok = t & 63;
        float ssum = 0.f;
        #pragma unroll
        for (int d = 0; d < 32; d++) {
            float v = S[tok*129 + head*32 + d];
            ssum += v*v;
        }
        rn[head*64 + tok] = 1.f / fmaxf(sqrtf(ssum), 1e-12f);
        __syncthreads();
    }

    float* dstw = dst + (size_t)win * NHEAD * NTOK * HDIM;
    #pragma unroll
    for (int i = 0; i < 8; i++) {
        int s4 = t + i*256;
        int o  = s4*4;
        int head = o >> 11;
        int tok  = (o >> 5) & 63;
        int d    = o & 31;
        float sc = do_norm ? rn[head*64 + tok] : 1.f;
        float4 v;
        v.x = S[tok*129 + head*32 + d + 0] * sc;
        v.y = S[tok*129 + head*32 + d + 1] * sc;
        v.z = S[tok*129 + head*32 + d + 2] * sc;
        v.w = S[tok*129 + head*32 + d + 3] * sc;
        *(float4*)(dstw + o) = v;
    }
}

// ---------------- attention (per window, 4 heads) ----------------
#define ATTN_SMEM_FLOATS (2112*3 + 4160*2 + 900)
__global__ __launch_bounds__(256) void attn_kernel(
    const float* __restrict__ rel_bias, const float* __restrict__ logit_scale,
    const float* __restrict__ gating)
{
    extern __shared__ float sm[];
    float* sq    = sm;
    float* sk    = sm + 2112;
    float* skr   = sm + 4224;     // later reused for V
    float* S1    = sm + 6336;
    float* S2    = sm + 6336 + 4160;
    float* sbias = sm + 6336 + 8320;

    const int t   = threadIdx.x;
    const int win = blockIdx.x;
    const int b   = win >> 10;
    const int hw  = (win & 1023) >> 5;
    const int ww  = win & 31;

    for (int i = t; i < 225*4; i += 256) sbias[i] = rel_bias[i];

    for (int head = 0; head < 4; head++) {
        float ls = __expf(fminf(logit_scale[head], 4.6051702f));
        float gt = 1.f / (1.f + __expf(-gating[head]));
        const size_t base = ((size_t)(win*4 + head)) * (NTOK*HDIM);

        #pragma unroll
        for (int i = 0; i < 2; i++) {
            int s = t + i*256;
            int tok = s >> 3, f4 = s & 7;
            float4 vq = *(const float4*)(g_qn  + base + tok*32 + f4*4);
            float4 vk = *(const float4*)(g_kn  + base + tok*32 + f4*4);
            float4 vr = *(const float4*)(g_knr + base + tok*32 + f4*4);
            int o = tok*33 + f4*4;
            sq[o+0]=vq.x; sq[o+1]=vq.y; sq[o+2]=vq.z; sq[o+3]=vq.w;
            sk[o+0]=vk.x; sk[o+1]=vk.y; sk[o+2]=vk.z; sk[o+3]=vk.w;
            skr[o+0]=vr.x; skr[o+1]=vr.y; skr[o+2]=vr.z; skr[o+3]=vr.w;
        }
        __syncthreads();

        const int tn = t >> 4, tm = t & 15;
        float a1[4][4], a2[4][4];
        #pragma unroll
        for (int i=0;i<4;i++)
            #pragma unroll
            for (int j=0;j<4;j++) { a1[i][j]=0.f; a2[i][j]=0.f; }
        for (int d = 0; d < 32; d++) {
            float q0 = sq[(tn*4+0)*33 + d];
            float q1 = sq[(tn*4+1)*33 + d];
            float q2 = sq[(tn*4+2)*33 + d];
            float q3 = sq[(tn*4+3)*33 + d];
            #pragma unroll
            for (int j = 0; j < 4; j++) {
                float kv = sk [(tm*4+j)*33 + d];
                float rv = skr[(tm*4+j)*33 + d];
                a1[0][j] += q0*kv; a1[1][j] += q1*kv; a1[2][j] += q2*kv; a1[3][j] += q3*kv;
                a2[0][j] += q0*rv; a2[1][j] += q1*rv; a2[2][j] += q2*rv; a2[3][j] += q3*rv;
            }
        }
        #pragma unroll
        for (int i = 0; i < 4; i++)
            #pragma unroll
            for (int j = 0; j < 4; j++) {
                int n = tn*4 + i, m = tm*4 + j;
                int ridx = ((n>>3) - (m>>3) + 7)*15 + ((n&7) - (m&7) + 7);
                float bs = sbias[ridx*4 + head];
                S1[n*65 + m] = a1[i][j]*ls + bs;
                S2[n*65 + m] = a2[i][j]*ls + bs;
            }
        __syncthreads();

        if (t < 128) {
            float* Sx = (t < 64) ? S1 : S2;
            int r = t & 63;
            float mx = Sx[r*65];
            for (int m = 1; m < 64; m++) mx = fmaxf(mx, Sx[r*65 + m]);
            float sum = 0.f;
            for (int m = 0; m < 64; m++) {
                float e = __expf(Sx[r*65 + m] - mx);
                Sx[r*65 + m] = e; sum += e;
            }
            float inv = 1.f / sum;
            for (int m = 0; m < 64; m++) Sx[r*65 + m] *= inv;
        }
        __syncthreads();

        #pragma unroll
        for (int u = 0; u < 16; u++) {
            int e = t*16 + u;
            int n = e >> 6, m = e & 63;
            S1[n*65 + m] = (1.f - gt)*S1[n*65 + m] + gt*S2[n*65 + m];
        }
        #pragma unroll
        for (int i = 0; i < 2; i++) {
            int s = t + i*256;
            int tok = s >> 3, f4 = s & 7;
            float4 vv = *(const float4*)(g_v + base + tok*32 + f4*4);
            int o = tok*33 + f4*4;
            skr[o+0]=vv.x; skr[o+1]=vv.y; skr[o+2]=vv.z; skr[o+3]=vv.w;
        }
        __syncthreads();

        {
            int n  = t >> 2;
            int d0 = (t & 3) * 8;
            float o[8];
            #pragma unroll
            for (int j = 0; j < 8; j++) o[j] = 0.f;
            for (int m = 0; m < 64; m++) {
                float a = S1[n*65 + m];
                #pragma unroll
                for (int j = 0; j < 8; j++) o[j] += a * skr[m*33 + d0 + j];
            }
            int i1 = n >> 3, j1 = n & 7;
            size_t pix = (((size_t)b*IMGH + hw*8 + i1)*IMGW + (ww*8 + j1)) * CDIM;
            *(float4*)(g_imgA + pix + head*32 + d0)     = make_float4(o[0],o[1],o[2],o[3]);
            *(float4*)(g_imgA + pix + head*32 + d0 + 4) = make_float4(o[4],o[5],o[6],o[7]);
        }
        __syncthreads();
    }
}

// ---------------- bf16 tensor-core conv3x3 ----------------
__device__ __forceinline__ float* img_by_id(int id) {
    return id == 0 ? g_imgA : (id == 1 ? g_imgB : g_imgC);
}

__device__ __forceinline__ void ldsm4(uint32_t* r, uint32_t addr) {
    asm volatile("ldmatrix.sync.aligned.m8n8.x4.shared.b16 {%0,%1,%2,%3}, [%4];"
        : "=r"(r[0]), "=r"(r[1]), "=r"(r[2]), "=r"(r[3]) : "r"(addr));
}
__device__ __forceinline__ void ldsm4t(uint32_t* r, uint32_t addr) {
    asm volatile("ldmatrix.sync.aligned.m8n8.x4.trans.shared.b16 {%0,%1,%2,%3}, [%4];"
        : "=r"(r[0]), "=r"(r[1]), "=r"(r[2]), "=r"(r[3]) : "r"(addr));
}
__device__ __forceinline__ void mma16816(float* c, const uint32_t* a, const uint32_t* b) {
    asm volatile("mma.sync.aligned.m16n8k16.row.col.f32.bf16.bf16.f32 "
        "{%0,%1,%2,%3}, {%4,%5,%6,%7}, {%8,%9}, {%0,%1,%2,%3};"
        : "+f"(c[0]), "+f"(c[1]), "+f"(c[2]), "+f"(c[3])
        : "r"(a[0]), "r"(a[1]), "r"(a[2]), "r"(a[3]), "r"(b[0]), "r"(b[1]));
}
__device__ __forceinline__ void cp_async16(uint32_t dst, const void* src) {
    asm volatile("cp.async.cg.shared.global [%0], [%1], 16;" :: "r"(dst), "l"(src));
}

// smem layout (bytes): A_hi [100 rows x 272B] @0, A_lo @27200,
//                      B stages @54400: stage*(8704) + {hi:0, lo:4352}, each 16x272B
#define CONV_SMEM_BYTES 71808
#define A_PITCH_B 272
#define A_PITCH_E 136

__global__ __launch_bounds__(256) void conv3x3_mma(
    int in_id, int conv_idx, const float* __restrict__ bias,
    int res_id, int out_id, int relu)
{
    extern __shared__ __align__(16) unsigned char smem_raw[];
    __nv_bfloat16* aHiP = reinterpret_cast<__nv_bfloat16*>(smem_raw);
    __nv_bfloat16* aLoP = aHiP + 13600;
    const uint32_t smem_u = (uint32_t)__cvta_generic_to_shared(smem_raw);
    const uint32_t aHiU = smem_u;
    const uint32_t aLoU = smem_u + 27200;
    const uint32_t bU   = smem_u + 54400;

    const float* in  = img_by_id(in_id);
    float*       out = img_by_id(out_id);
    const float* res = (res_id >= 0) ? img_by_id(res_id) : nullptr;
    const __nv_bfloat16* wHi = g_wbf_hi + (size_t)conv_idx * KCONV * 128;
    const __nv_bfloat16* wLo = g_wbf_lo + (size_t)conv_idx * KCONV * 128;

    const int t    = threadIdx.x;
    const int lane = t & 31;
    const int wid  = t >> 5;            // 0..7
    const int warpM = wid >> 2;         // 0..1  (rows of 32 pixels)
    const int warpN = wid & 3;          // 0..3  (cols of 32 channels)

    const int blk = blockIdx.x;
    const int b   = blk >> 10;
    const int th  = (blk & 1023) >> 5;
    const int tw  = blk & 31;
    const int h0  = th*8, w0 = tw*8;

    // ---- fill A halo tile 10x10x128, split to bf16 hi/lo ----
    for (int idx = t; idx < 3200; idx += 256) {
        int r  = idx >> 5;               // 0..99
        int c4 = idx & 31;               // float4 chunk
        int hh = h0 + (r/10) - 1;
        int ww = w0 + (r%10) - 1;
        float4 v = make_float4(0.f, 0.f, 0.f, 0.f);
        if (hh >= 0 && hh < IMGH && ww >= 0 && ww < IMGW)
            v = *(const float4*)(in + (((size_t)b*IMGH + hh)*IMGW + ww)*CDIM + c4*4);
        __nv_bfloat16 hx = __float2bfloat16(v.x), hy = __float2bfloat16(v.y);
        __nv_bfloat16 hz = __float2bfloat16(v.z), hw2 = __float2bfloat16(v.w);
        float lx = v.x - __bfloat162float(hx), ly = v.y - __bfloat162float(hy);
        float lz = v.z - __bfloat162float(hz), lw = v.w - __bfloat162float(hw2);
        uint32_t h01 = ((uint32_t)__bfloat16_as_ushort(hy) << 16) | __bfloat16_as_ushort(hx);
        uint32_t h23 = ((uint32_t)__bfloat16_as_ushort(hw2) << 16) | __bfloat16_as_ushort(hz);
        __nv_bfloat16 l0 = __float2bfloat16(lx), l1 = __float2bfloat16(ly);
        __nv_bfloat16 l2 = __float2bfloat16(lz), l3 = __float2bfloat16(lw);
        uint32_t lo01 = ((uint32_t)__bfloat16_as_ushort(l1) << 16) | __bfloat16_as_ushort(l0);
        uint32_t lo23 = ((uint32_t)__bfloat16_as_ushort(l3) << 16) | __bfloat16_as_ushort(l2);
        int off = r*A_PITCH_E + c4*4;
        *(uint32_t*)(aHiP + off)     = h01;
        *(uint32_t*)(aHiP + off + 2) = h23;
        *(uint32_t*)(aLoP + off)     = lo01;
        *(uint32_t*)(aLoP + off + 2) = lo23;
    }

    // ---- B prefetch lambda: kstep ks into stage ----
    const int prow = t >> 4;   // 0..15
    const int pseg = t & 15;   // 0..15
    auto prefetchB = [&](int ks, int stage) {
        size_t gofs = ((size_t)(ks*16 + prow))*128 + pseg*8;
        uint32_t d = bU + stage*8704 + prow*A_PITCH_B + pseg*16;
        cp_async16(d,        wHi + gofs);
        cp_async16(d + 4352, wLo + gofs);
    };

    prefetchB(0, 0);
    asm volatile("cp.async.commit_group;");
    __syncthreads();   // A tile ready

    float acc[2][4][4];
    #pragma unroll
    for (int mi = 0; mi < 2; mi++)
        #pragma unroll
        for (int ni = 0; ni < 4; ni++)
            #pragma unroll
            for (int e = 0; e < 4; e++) acc[mi][ni][e] = 0.f;

    for (int ks = 0; ks < 72; ks++) {
        const int stage = ks & 1;
        if (ks < 71) {
            prefetchB(ks + 1, stage ^ 1);
            asm volatile("cp.async.commit_group;");
            asm volatile("cp.async.wait_group 1;");
        } else {
            asm volatile("cp.async.wait_group 0;");
        }
        __syncthreads();

        const int tap = ks >> 3;
        const int kc  = (ks & 7) << 4;
        const int dy  = tap / 3;     // 0..2 (halo offset built in)
        const int dx  = tap - dy*3;

        // A fragments
        uint32_t a_hi[2][4], a_lo[2][4];
        #pragma unroll
        for (int mi = 0; mi < 2; mi++) {
            int p = warpM*32 + mi*16 + (lane & 15);
            int r = ((p >> 3) + dy)*10 + (p & 7) + dx;
            uint32_t off = (uint32_t)(r*A_PITCH_B + (kc + ((lane >> 4) << 3))*2);
            ldsm4(a_hi[mi], aHiU + off);
            ldsm4(a_lo[mi], aLoU + off);
        }

        // B fragments
        uint32_t b_hi[4][2], b_lo[4][2];
        const uint32_t bst = bU + stage*8704;
        #pragma unroll
        for (int pair = 0; pair < 2; pair++) {
            uint32_t off = (uint32_t)((lane & 15)*A_PITCH_B +
                           (warpN*32 + pair*16 + ((lane >> 4) << 3))*2);
            uint32_t r4[4];
            ldsm4t(r4, bst + off);
            b_hi[pair*2][0] = r4[0]; b_hi[pair*2][1] = r4[1];
            b_hi[pair*2+1][0] = r4[2]; b_hi[pair*2+1][1] = r4[3];
            ldsm4t(r4, bst + 4352 + off);
            b_lo[pair*2][0] = r4[0]; b_lo[pair*2][1] = r4[1];
            b_lo[pair*2+1][0] = r4[2]; b_lo[pair*2+1][1] = r4[3];
        }

        #pragma unroll
        for (int mi = 0; mi < 2; mi++)
            #pragma unroll
            for (int ni = 0; ni < 4; ni++) {
                mma16816(acc[mi][ni], a_hi[mi], b_hi[ni]);
                mma16816(acc[mi][ni], a_hi[mi], b_lo[ni]);
                mma16816(acc[mi][ni], a_lo[mi], b_hi[ni]);
            }
        __syncthreads();
    }

    // ---- epilogue: bias / relu / residual, write to image ----
    #pragma unroll
    for (int mi = 0; mi < 2; mi++) {
        #pragma unroll
        for (int ni = 0; ni < 4; ni++) {
            int p0 = warpM*32 + mi*16 + (lane >> 2);
            int p1 = p0 + 8;
            int ch = warpN*32 + ni*8 + (lane & 3)*2;
            float2 bb = *(const float2*)(bias + ch);
            float v00 = acc[mi][ni][0] + bb.x, v01 = acc[mi][ni][1] + bb.y;
            float v10 = acc[mi][ni][2] + bb.x, v11 = acc[mi][ni][3] + bb.y;
            if (relu) {
                v00 = fmaxf(v00, 0.f); v01 = fmaxf(v01, 0.f);
                v10 = fmaxf(v10, 0.f); v11 = fmaxf(v11, 0.f);
            }
            size_t g0 = (((size_t)b*IMGH + h0 + (p0 >> 3))*IMGW + w0 + (p0 & 7))*CDIM + ch;
            size_t g1 = (((size_t)b*IMGH + h0 + (p1 >> 3))*IMGW + w0 + (p1 & 7))*CDIM + ch;
            if (res) {
                float2 r0 = *(const float2*)(res + g0);
                float2 r1 = *(const float2*)(res + g1);
                v00 += r0.x; v01 += r0.y; v10 += r1.x; v11 += r1.y;
            }
            *(float2*)(out + g0) = make_float2(v00, v01);
            *(float2*)(out + g1) = make_float2(v10, v11);
        }
    }
}

// ---------------- proj 1x1 + window_partition -> d_out ----------------
__global__ __launch_bounds__(256) void proj_kernel(
    const float* __restrict__ proj_b, float* __restrict__ out)
{
    __shared__ float sA[32*65];
    __shared__ float sB[32*128];

    const float* img = g_imgA;

    const int t   = threadIdx.x;
    const int win = blockIdx.x;
    const int b   = win >> 10;
    const int hw  = (win & 1023) >> 5;
    const int ww  = win & 31;
    const int ty  = t >> 4, tx = t & 15;
    const int ty4 = ty*4,  tx8 = tx*8;

    float acc[4][8];
    #pragma unroll
    for (int i = 0; i < 4; i++)
        #pragma unroll
        for (int j = 0; j < 8; j++) acc[i][j] = 0.f;

    for (int kc = 0; kc < 128; kc += 32) {
        #pragma unroll
        for (int i = 0; i < 2; i++) {
            int s = t + i*256;
            int tok = s >> 3, f4 = s & 7;
            int i1 = tok >> 3, j1 = tok & 7;
            size_t pix = (((size_t)b*IMGH + hw*8 + i1)*IMGW + (ww*8 + j1))*CDIM;
            float4 v = *(const float4*)(img + pix + kc + f4*4);
            sA[(f4*4+0)*65 + tok] = v.x;
            sA[(f4*4+1)*65 + tok] = v.y;
            sA[(f4*4+2)*65 + tok] = v.z;
            sA[(f4*4+3)*65 + tok] = v.w;
        }
        #pragma unroll
        for (int i = 0; i < 4; i++) {
            int s = t + i*256;
            int kk = s >> 5, cg = s & 31;
            *(float4*)(sB + kk*128 + cg*4) =
                *(const float4*)(g_wt_proj + (kc+kk)*128 + cg*4);
        }
        __syncthreads();
        #pragma unroll
        for (int kk = 0; kk < 32; kk++) {
            float a0 = sA[kk*65 + ty4 + 0];
            float a1 = sA[kk*65 + ty4 + 1];
            float a2 = sA[kk*65 + ty4 + 2];
            float a3 = sA[kk*65 + ty4 + 3];
            float4 b0 = *(const float4*)(sB + kk*128 + tx8);
            float4 b1 = *(const float4*)(sB + kk*128 + tx8 + 4);
            FMA_ROW(0, a0) FMA_ROW(1, a1) FMA_ROW(2, a2) FMA_ROW(3, a3)
        }
        __syncthreads();
    }

    #pragma unroll
    for (int i = 0; i < 4; i++) {
        int tok = ty4 + i;
        size_t obase = ((size_t)win*NTOK + tok)*CDIM + tx8;
        float4 v0, v1;
        v0.x = acc[i][0] + proj_b[tx8+0]; v0.y = acc[i][1] + proj_b[tx8+1];
        v0.z = acc[i][2] + proj_b[tx8+2]; v0.w = acc[i][3] + proj_b[tx8+3];
        v1.x = acc[i][4] + proj_b[tx8+4]; v1.y = acc[i][5] + proj_b[tx8+5];
        v1.z = acc[i][6] + proj_b[tx8+6]; v1.w = acc[i][7] + proj_b[tx8+7];
        *(float4*)(out + obase)     = v0;
        *(float4*)(out + obase + 4) = v1;
    }
}

// ---------------- launch ----------------
extern "C" void kernel_launch(void* const* d_in, const int* in_sizes, int n_in,
                              void* d_out, int out_size) {
    const float* x         = (const float*)d_in[0];
    const float* ref       = (const float*)d_in[1];
    const float* qkv_w     = (const float*)d_in[2];
    const float* qkv_b     = (const float*)d_in[3];
    const float* proj_w    = (const float*)d_in[4];
    const float* proj_b    = (const float*)d_in[5];
    const float* t11w      = (const float*)d_in[6];
    const float* t11b      = (const float*)d_in[7];
    const float* t12w      = (const float*)d_in[8];
    const float* t12b      = (const float*)d_in[9];
    const float* t21w      = (const float*)d_in[10];
    const float* t21b      = (const float*)d_in[11];
    const float* t22w      = (const float*)d_in[12];
    const float* t22b      = (const float*)d_in[13];
    const float* rel_bias  = (const float*)d_in[14];
    const float* logit_sc  = (const float*)d_in[15];
    const float* gating    = (const float*)d_in[16];
    float* out = (float*)d_out;

    float *qn, *kn, *knr, *v;
    cudaGetSymbolAddress((void**)&qn,  g_qn);
    cudaGetSymbolAddress((void**)&kn,  g_kn);
    cudaGetSymbolAddress((void**)&knr, g_knr);
    cudaGetSymbolAddress((void**)&v,   g_v);

    cudaFuncSetAttribute(attn_kernel, cudaFuncAttributeMaxDynamicSharedMemorySize,
                         ATTN_SMEM_FLOATS * (int)sizeof(float));
    cudaFuncSetAttribute(conv3x3_mma, cudaFuncAttributeMaxDynamicSharedMemorySize,
                         CONV_SMEM_BYTES);

    transpose_weights<<<192, 256>>>(qkv_w, proj_w);
    split_weights<<<(KCONV*128 + 255)/256, 256>>>(t11w, t12w, t21w, t22w);

    qkv_kernel<<<NWIN, 256>>>(x,   qkv_b, qn,  0, 1);
    qkv_kernel<<<NWIN, 256>>>(x,   qkv_b, kn,  1, 1);
    qkv_kernel<<<NWIN, 256>>>(x,   qkv_b, v,   2, 0);
    qkv_kernel<<<NWIN, 256>>>(ref, qkv_b, knr, 1, 1);

    attn_kernel<<<NWIN, 256, ATTN_SMEM_FLOATS * (int)sizeof(float)>>>(rel_bias, logit_sc, gating);

    // conv chain: A -> B(relu) -> C(+A) -> B(relu) -> A(+C)
    conv3x3_mma<<<NWIN, 256, CONV_SMEM_BYTES>>>(0, 0, t11b, -1, 1, 1);
    conv3x3_mma<<<NWIN, 256, CONV_SMEM_BYTES>>>(1, 1, t12b,  0, 2, 0);
    conv3x3_mma<<<NWIN, 256, CONV_SMEM_BYTES>>>(2, 2, t21b, -1, 1, 1);
    conv3x3_mma<<<NWIN, 256, CONV_SMEM_BYTES>>>(1, 3, t22b,  2, 0, 0);

    proj_kernel<<<NWIN, 256>>>(proj_b, out);
}

// round 4
// speedup vs baseline: 3.3401x; 1.2497x over previous
#include <cuda_runtime.h>
#include <cuda_bf16.h>
#include <cstdint>
#include <cstddef>

// ---------------- constants ----------------
#define NWIN   2048
#define NTOK   64
#define CDIM   128
#define NHEAD  4
#define HDIM   32
#define IMGH   256
#define IMGW   256
#define NB     2
#define KCONV  1152          // 9*128

// ---------------- scratch ----------------
__device__ float g_qn [NWIN*NHEAD*NTOK*HDIM];
__device__ float g_kn [NWIN*NHEAD*NTOK*HDIM];
__device__ float g_knr[NWIN*NHEAD*NTOK*HDIM];
__device__ float g_v  [NWIN*NHEAD*NTOK*HDIM];
__device__ float g_imgA[(size_t)NB*IMGH*IMGW*CDIM];
__device__ float g_imgB[(size_t)NB*IMGH*IMGW*CDIM];
__device__ float g_imgC[(size_t)NB*IMGH*IMGW*CDIM];
__device__ __nv_bfloat16 g_wbf_hi[4*KCONV*128];   // conv weights [conv][k][o]
__device__ __nv_bfloat16 g_wbf_lo[4*KCONV*128];
__device__ __nv_bfloat16 g_wqkv_hi[128*384];      // [k][o]
__device__ __nv_bfloat16 g_wqkv_lo[128*384];
__device__ __nv_bfloat16 g_wproj_hi[128*128];     // [k][o]
__device__ __nv_bfloat16 g_wproj_lo[128*128];

// ---------------- weight prep: transpose + hi/lo split ----------------
__global__ void prep_weights(const float* __restrict__ qkv_w,
                             const float* __restrict__ proj_w) {
    int t = blockIdx.x * blockDim.x + threadIdx.x;   // 0..49151
    if (t < 384*128) {
        int o = t / 128, k = t % 128;
        float x = qkv_w[t];
        __nv_bfloat16 hi = __float2bfloat16(x);
        g_wqkv_hi[k*384 + o] = hi;
        g_wqkv_lo[k*384 + o] = __float2bfloat16(x - __bfloat162float(hi));
    }
    if (t < 128*128) {
        int o = t / 128, k = t % 128;
        float x = proj_w[t];
        __nv_bfloat16 hi = __float2bfloat16(x);
        g_wproj_hi[k*128 + o] = hi;
        g_wproj_lo[k*128 + o] = __float2bfloat16(x - __bfloat162float(hi));
    }
}

__global__ void split_weights(const float* __restrict__ w0, const float* __restrict__ w1,
                              const float* __restrict__ w2, const float* __restrict__ w3) {
    int t = blockIdx.x * blockDim.x + threadIdx.x;
    if (t >= KCONV*128) return;
    const float* ws[4] = {w0, w1, w2, w3};
    #pragma unroll
    for (int c = 0; c < 4; c++) {
        float x = ws[c][t];
        __nv_bfloat16 hi = __float2bfloat16(x);
        float lo = x - __bfloat162float(hi);
        g_wbf_hi[c*KCONV*128 + t] = hi;
        g_wbf_lo[c*KCONV*128 + t] = __float2bfloat16(lo);
    }
}

// ---------------- mma helpers ----------------
__device__ __forceinline__ void ldsm4(uint32_t* r, uint32_t addr) {
    asm volatile("ldmatrix.sync.aligned.m8n8.x4.shared.b16 {%0,%1,%2,%3}, [%4];"
        : "=r"(r[0]), "=r"(r[1]), "=r"(r[2]), "=r"(r[3]) : "r"(addr));
}
__device__ __forceinline__ void ldsm4t(uint32_t* r, uint32_t addr) {
    asm volatile("ldmatrix.sync.aligned.m8n8.x4.trans.shared.b16 {%0,%1,%2,%3}, [%4];"
        : "=r"(r[0]), "=r"(r[1]), "=r"(r[2]), "=r"(r[3]) : "r"(addr));
}
__device__ __forceinline__ void mma16816(float* c, const uint32_t* a, const uint32_t* b) {
    asm volatile("mma.sync.aligned.m16n8k16.row.col.f32.bf16.bf16.f32 "
        "{%0,%1,%2,%3}, {%4,%5,%6,%7}, {%8,%9}, {%0,%1,%2,%3};"
        : "+f"(c[0]), "+f"(c[1]), "+f"(c[2]), "+f"(c[3])
        : "r"(a[0]), "r"(a[1]), "r"(a[2]), "r"(a[3]), "r"(b[0]), "r"(b[1]));
}
__device__ __forceinline__ void cp_async16(uint32_t dst, const void* src) {
    asm volatile("cp.async.cg.shared.global [%0], [%1], 16;" :: "r"(dst), "l"(src));
}
__device__ __forceinline__ void split_store(__nv_bfloat16* hiP, __nv_bfloat16* loP,
                                            int off, float4 v) {
    __nv_bfloat16 hx = __float2bfloat16(v.x), hy = __float2bfloat16(v.y);
    __nv_bfloat16 hz = __float2bfloat16(v.z), hw = __float2bfloat16(v.w);
    uint32_t h01 = ((uint32_t)__bfloat16_as_ushort(hy) << 16) | __bfloat16_as_ushort(hx);
    uint32_t h23 = ((uint32_t)__bfloat16_as_ushort(hw) << 16) | __bfloat16_as_ushort(hz);
    __nv_bfloat16 l0 = __float2bfloat16(v.x - __bfloat162float(hx));
    __nv_bfloat16 l1 = __float2bfloat16(v.y - __bfloat162float(hy));
    __nv_bfloat16 l2 = __float2bfloat16(v.z - __bfloat162float(hz));
    __nv_bfloat16 l3 = __float2bfloat16(v.w - __bfloat162float(hw));
    uint32_t lo01 = ((uint32_t)__bfloat16_as_ushort(l1) << 16) | __bfloat16_as_ushort(l0);
    uint32_t lo23 = ((uint32_t)__bfloat16_as_ushort(l3) << 16) | __bfloat16_as_ushort(l2);
    *(uint32_t*)(hiP + off)     = h01;
    *(uint32_t*)(hiP + off + 2) = h23;
    *(uint32_t*)(loP + off)     = lo01;
    *(uint32_t*)(loP + off + 2) = lo23;
}

// ================= fused QKV (x branch): GEMM 64x384x128 + per-head norm =================
// smem: aHi 64x136 bf16 @0 (17408B), aLo @17408, B stages @34816 (2 x 25088: hi 16x392, lo)
#define QKV_SMEM 84992
__global__ __launch_bounds__(256) void qkv_mma(
    const float* __restrict__ src, const float* __restrict__ qkv_b)
{
    extern __shared__ __align__(16) unsigned char smem_raw[];
    __nv_bfloat16* aHiP = reinterpret_cast<__nv_bfloat16*>(smem_raw);
    __nv_bfloat16* aLoP = aHiP + 64*136;
    const uint32_t smem_u = (uint32_t)__cvta_generic_to_shared(smem_raw);
    const uint32_t aHiU = smem_u, aLoU = smem_u + 17408, bU = smem_u + 34816;

    const int t = threadIdx.x, lane = t & 31, wid = t >> 5;
    const int warpM = wid >> 2, warpN = wid & 3;   // 2 x 4, warp tile 32 x 96
    const int win = blockIdx.x;
    const float* srcw = src + (size_t)win * NTOK * CDIM;

    for (int idx = t; idx < 2048; idx += 256) {
        int r = idx >> 5, c4 = idx & 31;
        float4 v = *(const float4*)(srcw + r*128 + c4*4);
        split_store(aHiP, aLoP, r*136 + c4*4, v);
    }

    auto prefetchB = [&](int ks, int stage) {
        #pragma unroll
        for (int i = 0; i < 6; i++) {
            int c = t + i*256;
            int part = c >= 768; int cc = c - part*768;
            int row = cc / 48, seg = cc % 48;
            const __nv_bfloat16* sp = (part ? g_wqkv_lo : g_wqkv_hi) + (ks*16 + row)*384 + seg*8;
            cp_async16(bU + stage*25088 + part*12544 + row*784 + seg*16, sp);
        }
    };
    prefetchB(0, 0);
    asm volatile("cp.async.commit_group;");
    __syncthreads();

    float acc[2][12][4];
    #pragma unroll
    for (int mi = 0; mi < 2; mi++)
        #pragma unroll
        for (int ni = 0; ni < 12; ni++)
            #pragma unroll
            for (int e = 0; e < 4; e++) acc[mi][ni][e] = 0.f;

    for (int ks = 0; ks < 8; ks++) {
        const int stage = ks & 1;
        if (ks < 7) {
            prefetchB(ks + 1, stage ^ 1);
            asm volatile("cp.async.commit_group;");
            asm volatile("cp.async.wait_group 1;");
        } else {
            asm volatile("cp.async.wait_group 0;");
        }
        __syncthreads();

        const int kc = ks * 16;
        uint32_t a_hi[2][4], a_lo[2][4];
        #pragma unroll
        for (int mi = 0; mi < 2; mi++) {
            int row = warpM*32 + mi*16 + (lane & 15);
            uint32_t off = (uint32_t)(row*272 + (kc + ((lane >> 4) << 3))*2);
            ldsm4(a_hi[mi], aHiU + off);
            ldsm4(a_lo[mi], aLoU + off);
        }
        const uint32_t bst = bU + stage*25088;
        #pragma unroll
        for (int pair = 0; pair < 6; pair++) {
            uint32_t off = (uint32_t)((lane & 15)*784 +
                           (warpN*96 + pair*16 + ((lane >> 4) << 3))*2);
            uint32_t bh[4], bl[4];
            ldsm4t(bh, bst + off);
            ldsm4t(bl, bst + 12544 + off);
            #pragma unroll
            for (int mi = 0; mi < 2; mi++) {
                mma16816(acc[mi][2*pair],   a_hi[mi], bh);
                mma16816(acc[mi][2*pair],   a_hi[mi], bl);
                mma16816(acc[mi][2*pair],   a_lo[mi], bh);
                mma16816(acc[mi][2*pair+1], a_hi[mi], bh+2);
                mma16816(acc[mi][2*pair+1], a_hi[mi], bl+2);
                mma16816(acc[mi][2*pair+1], a_lo[mi], bh+2);
            }
        }
        __syncthreads();
    }

    // epilogue: bias, per-head L2 norm (q,k) via warp shfl, scatter to head layout
    #pragma unroll
    for (int mi = 0; mi < 2; mi++) {
        int row0 = warpM*32 + mi*16 + (lane >> 2);
        int row1 = row0 + 8;
        #pragma unroll
        for (int ni = 0; ni < 12; ni++) {
            int col = warpN*96 + ni*8 + (lane & 3)*2;
            float2 bb = *(const float2*)(qkv_b + col);
            acc[mi][ni][0] += bb.x; acc[mi][ni][1] += bb.y;
            acc[mi][ni][2] += bb.x; acc[mi][ni][3] += bb.y;
        }
        #pragma unroll
        for (int sg = 0; sg < 3; sg++) {
            float s0 = 0.f, s1 = 0.f;
            #pragma unroll
            for (int k = 0; k < 4; k++) {
                int ni = sg*4 + k;
                s0 += acc[mi][ni][0]*acc[mi][ni][0] + acc[mi][ni][1]*acc[mi][ni][1];
                s1 += acc[mi][ni][2]*acc[mi][ni][2] + acc[mi][ni][3]*acc[mi][ni][3];
            }
            s0 += __shfl_xor_sync(0xffffffffu, s0, 1);
            s0 += __shfl_xor_sync(0xffffffffu, s0, 2);
            s1 += __shfl_xor_sync(0xffffffffu, s1, 1);
            s1 += __shfl_xor_sync(0xffffffffu, s1, 2);
            int gcol = warpN*96 + sg*32;
            int sec = gcol >> 7, head = (gcol >> 5) & 3;
            float sc0 = 1.f, sc1 = 1.f;
            if (sec < 2) {
                sc0 = 1.f / fmaxf(sqrtf(s0), 1e-12f);
                sc1 = 1.f / fmaxf(sqrtf(s1), 1e-12f);
            }
            float* dst = (sec == 0) ? g_qn : (sec == 1 ? g_kn : g_v);
            float* base = dst + (size_t)win*8192 + head*2048;
            #pragma unroll
            for (int k = 0; k < 4; k++) {
                int ni = sg*4 + k;
                int d = k*8 + (lane & 3)*2;
                *(float2*)(base + row0*32 + d) =
                    make_float2(acc[mi][ni][0]*sc0, acc[mi][ni][1]*sc0);
                *(float2*)(base + row1*32 + d) =
                    make_float2(acc[mi][ni][2]*sc1, acc[mi][ni][3]*sc1);
            }
        }
    }
}

// ================= k_ref: GEMM 64x128x128 (weight cols 128..255) + norm =================
// smem: aHi/aLo 34816, B stages @34816 (2 x 8704)
#define KREF_SMEM 52224
__global__ __launch_bounds__(256) void kref_mma(
    const float* __restrict__ src, const float* __restrict__ qkv_b)
{
    extern __shared__ __align__(16) unsigned char smem_raw[];
    __nv_bfloat16* aHiP = reinterpret_cast<__nv_bfloat16*>(smem_raw);
    __nv_bfloat16* aLoP = aHiP + 64*136;
    const uint32_t smem_u = (uint32_t)__cvta_generic_to_shared(smem_raw);
    const uint32_t aHiU = smem_u, aLoU = smem_u + 17408, bU = smem_u + 34816;

    const int t = threadIdx.x, lane = t & 31, wid = t >> 5;
    const int warpM = wid >> 2, warpN = wid & 3;   // warp tile 32 x 32 (one head)
    const int win = blockIdx.x;
    const float* srcw = src + (size_t)win * NTOK * CDIM;

    for (int idx = t; idx < 2048; idx += 256) {
        int r = idx >> 5, c4 = idx & 31;
        float4 v = *(const float4*)(srcw + r*128 + c4*4);
        split_store(aHiP, aLoP, r*136 + c4*4, v);
    }

    auto prefetchB = [&](int ks, int stage) {
        #pragma unroll
        for (int i = 0; i < 2; i++) {
            int c = t + i*256;
            int part = c >= 256; int cc = c - part*256;
            int row = cc >> 4, seg = cc & 15;
            const __nv_bfloat16* sp = (part ? g_wqkv_lo : g_wqkv_hi) + (ks*16 + row)*384 + 128 + seg*8;
            cp_async16(bU + stage*8704 + part*4352 + row*272 + seg*16, sp);
        }
    };
    prefetchB(0, 0);
    asm volatile("cp.async.commit_group;");
    __syncthreads();

    float acc[2][4][4];
    #pragma unroll
    for (int mi = 0; mi < 2; mi++)
        #pragma unroll
        for (int ni = 0; ni < 4; ni++)
            #pragma unroll
            for (int e = 0; e < 4; e++) acc[mi][ni][e] = 0.f;

    for (int ks = 0; ks < 8; ks++) {
        const int stage = ks & 1;
        if (ks < 7) {
            prefetchB(ks + 1, stage ^ 1);
            asm volatile("cp.async.commit_group;");
            asm volatile("cp.async.wait_group 1;");
        } else {
            asm volatile("cp.async.wait_group 0;");
        }
        __syncthreads();

        const int kc = ks * 16;
        uint32_t a_hi[2][4], a_lo[2][4];
        #pragma unroll
        for (int mi = 0; mi < 2; mi++) {
            int row = warpM*32 + mi*16 + (lane & 15);
            uint32_t off = (uint32_t)(row*272 + (kc + ((lane >> 4) << 3))*2);
            ldsm4(a_hi[mi], aHiU + off);
            ldsm4(a_lo[mi], aLoU + off);
        }
        const uint32_t bst = bU + stage*8704;
        #pragma unroll
        for (int pair = 0; pair < 2; pair++) {
            uint32_t off = (uint32_t)((lane & 15)*272 +
                           (warpN*32 + pair*16 + ((lane >> 4) << 3))*2);
            uint32_t bh[4], bl[4];
            ldsm4t(bh, bst + off);
            ldsm4t(bl, bst + 4352 + off);
            #pragma unroll
            for (int mi = 0; mi < 2; mi++) {
                mma16816(acc[mi][2*pair],   a_hi[mi], bh);
                mma16816(acc[mi][2*pair],   a_hi[mi], bl);
                mma16816(acc[mi][2*pair],   a_lo[mi], bh);
                mma16816(acc[mi][2*pair+1], a_hi[mi], bh+2);
                mma16816(acc[mi][2*pair+1], a_hi[mi], bl+2);
                mma16816(acc[mi][2*pair+1], a_lo[mi], bh+2);
            }
        }
        __syncthreads();
    }

    #pragma unroll
    for (int mi = 0; mi < 2; mi++) {
        int row0 = warpM*32 + mi*16 + (lane >> 2);
        int row1 = row0 + 8;
        #pragma unroll
        for (int ni = 0; ni < 4; ni++) {
            int col = warpN*32 + ni*8 + (lane & 3)*2;
            float2 bb = *(const float2*)(qkv_b + 128 + col);
            acc[mi][ni][0] += bb.x; acc[mi][ni][1] += bb.y;
            acc[mi][ni][2] += bb.x; acc[mi][ni][3] += bb.y;
        }
        float s0 = 0.f, s1 = 0.f;
        #pragma unroll
        for (int ni = 0; ni < 4; ni++) {
            s0 += acc[mi][ni][0]*acc[mi][ni][0] + acc[mi][ni][1]*acc[mi][ni][1];
            s1 += acc[mi][ni][2]*acc[mi][ni][2] + acc[mi][ni][3]*acc[mi][ni][3];
        }
        s0 += __shfl_xor_sync(0xffffffffu, s0, 1);
        s0 += __shfl_xor_sync(0xffffffffu, s0, 2);
        s1 += __shfl_xor_sync(0xffffffffu, s1, 1);
        s1 += __shfl_xor_sync(0xffffffffu, s1, 2);
        float sc0 = 1.f / fmaxf(sqrtf(s0), 1e-12f);
        float sc1 = 1.f / fmaxf(sqrtf(s1), 1e-12f);
        float* base = g_knr + (size_t)win*8192 + warpN*2048;
        #pragma unroll
        for (int ni = 0; ni < 4; ni++) {
            int d = ni*8 + (lane & 3)*2;
            *(float2*)(base + row0*32 + d) =
                make_float2(acc[mi][ni][0]*sc0, acc[mi][ni][1]*sc0);
            *(float2*)(base + row1*32 + d) =
                make_float2(acc[mi][ni][2]*sc1, acc[mi][ni][3]*sc1);
        }
    }
}

// ---------------- attention (per window, 4 heads) — unchanged ----------------
#define ATTN_SMEM_FLOATS (2112*3 + 4160*2 + 900)
__global__ __launch_bounds__(256) void attn_kernel(
    const float* __restrict__ rel_bias, const float* __restrict__ logit_scale,
    const float* __restrict__ gating)
{
    extern __shared__ float sm[];
    float* sq    = sm;
    float* sk    = sm + 2112;
    float* skr   = sm + 4224;
    float* S1    = sm + 6336;
    float* S2    = sm + 6336 + 4160;
    float* sbias = sm + 6336 + 8320;

    const int t   = threadIdx.x;
    const int win = blockIdx.x;
    const int b   = win >> 10;
    const int hw  = (win & 1023) >> 5;
    const int ww  = win & 31;

    for (int i = t; i < 225*4; i += 256) sbias[i] = rel_bias[i];

    for (int head = 0; head < 4; head++) {
        float ls = __expf(fminf(logit_scale[head], 4.6051702f));
        float gt = 1.f / (1.f + __expf(-gating[head]));
        const size_t base = ((size_t)(win*4 + head)) * (NTOK*HDIM);

        #pragma unroll
        for (int i = 0; i < 2; i++) {
            int s = t + i*256;
            int tok = s >> 3, f4 = s & 7;
            float4 vq = *(const float4*)(g_qn  + base + tok*32 + f4*4);
            float4 vk = *(const float4*)(g_kn  + base + tok*32 + f4*4);
            float4 vr = *(const float4*)(g_knr + base + tok*32 + f4*4);
            int o = tok*33 + f4*4;
            sq[o+0]=vq.x; sq[o+1]=vq.y; sq[o+2]=vq.z; sq[o+3]=vq.w;
            sk[o+0]=vk.x; sk[o+1]=vk.y; sk[o+2]=vk.z; sk[o+3]=vk.w;
            skr[o+0]=vr.x; skr[o+1]=vr.y; skr[o+2]=vr.z; skr[o+3]=vr.w;
        }
        __syncthreads();

        const int tn = t >> 4, tm = t & 15;
        float a1[4][4], a2[4][4];
        #pragma unroll
        for (int i=0;i<4;i++)
            #pragma unroll
            for (int j=0;j<4;j++) { a1[i][j]=0.f; a2[i][j]=0.f; }
        for (int d = 0; d < 32; d++) {
            float q0 = sq[(tn*4+0)*33 + d];
            float q1 = sq[(tn*4+1)*33 + d];
            float q2 = sq[(tn*4+2)*33 + d];
            float q3 = sq[(tn*4+3)*33 + d];
            #pragma unroll
            for (int j = 0; j < 4; j++) {
                float kv = sk [(tm*4+j)*33 + d];
                float rv = skr[(tm*4+j)*33 + d];
                a1[0][j] += q0*kv; a1[1][j] += q1*kv; a1[2][j] += q2*kv; a1[3][j] += q3*kv;
                a2[0][j] += q0*rv; a2[1][j] += q1*rv; a2[2][j] += q2*rv; a2[3][j] += q3*rv;
            }
        }
        #pragma unroll
        for (int i = 0; i < 4; i++)
            #pragma unroll
            for (int j = 0; j < 4; j++) {
                int n = tn*4 + i, m = tm*4 + j;
                int ridx = ((n>>3) - (m>>3) + 7)*15 + ((n&7) - (m&7) + 7);
                float bs = sbias[ridx*4 + head];
                S1[n*65 + m] = a1[i][j]*ls + bs;
                S2[n*65 + m] = a2[i][j]*ls + bs;
            }
        __syncthreads();

        if (t < 128) {
            float* Sx = (t < 64) ? S1 : S2;
            int r = t & 63;
            float mx = Sx[r*65];
            for (int m = 1; m < 64; m++) mx = fmaxf(mx, Sx[r*65 + m]);
            float sum = 0.f;
            for (int m = 0; m < 64; m++) {
                float e = __expf(Sx[r*65 + m] - mx);
                Sx[r*65 + m] = e; sum += e;
            }
            float inv = 1.f / sum;
            for (int m = 0; m < 64; m++) Sx[r*65 + m] *= inv;
        }
        __syncthreads();

        #pragma unroll
        for (int u = 0; u < 16; u++) {
            int e = t*16 + u;
            int n = e >> 6, m = e & 63;
            S1[n*65 + m] = (1.f - gt)*S1[n*65 + m] + gt*S2[n*65 + m];
        }
        #pragma unroll
        for (int i = 0; i < 2; i++) {
            int s = t + i*256;
            int tok = s >> 3, f4 = s & 7;
            float4 vv = *(const float4*)(g_v + base + tok*32 + f4*4);
            int o = tok*33 + f4*4;
            skr[o+0]=vv.x; skr[o+1]=vv.y; skr[o+2]=vv.z; skr[o+3]=vv.w;
        }
        __syncthreads();

        {
            int n  = t >> 2;
            int d0 = (t & 3) * 8;
            float o[8];
            #pragma unroll
            for (int j = 0; j < 8; j++) o[j] = 0.f;
            for (int m = 0; m < 64; m++) {
                float a = S1[n*65 + m];
                #pragma unroll
                for (int j = 0; j < 8; j++) o[j] += a * skr[m*33 + d0 + j];
            }
            int i1 = n >> 3, j1 = n & 7;
            size_t pix = (((size_t)b*IMGH + hw*8 + i1)*IMGW + (ww*8 + j1)) * CDIM;
            *(float4*)(g_imgA + pix + head*32 + d0)     = make_float4(o[0],o[1],o[2],o[3]);
            *(float4*)(g_imgA + pix + head*32 + d0 + 4) = make_float4(o[4],o[5],o[6],o[7]);
        }
        __syncthreads();
    }
}

// ---------------- bf16 tensor-core conv3x3 — unchanged ----------------
__device__ __forceinline__ float* img_by_id(int id) {
    return id == 0 ? g_imgA : (id == 1 ? g_imgB : g_imgC);
}

#define CONV_SMEM_BYTES 71808
#define A_PITCH_B 272
#define A_PITCH_E 136

__global__ __launch_bounds__(256) void conv3x3_mma(
    int in_id, int conv_idx, const float* __restrict__ bias,
    int res_id, int out_id, int relu)
{
    extern __shared__ __align__(16) unsigned char smem_raw[];
    __nv_bfloat16* aHiP = reinterpret_cast<__nv_bfloat16*>(smem_raw);
    __nv_bfloat16* aLoP = aHiP + 13600;
    const uint32_t smem_u = (uint32_t)__cvta_generic_to_shared(smem_raw);
    const uint32_t aHiU = smem_u;
    const uint32_t aLoU = smem_u + 27200;
    const uint32_t bU   = smem_u + 54400;

    const float* in  = img_by_id(in_id);
    float*       out = img_by_id(out_id);
    const float* res = (res_id >= 0) ? img_by_id(res_id) : nullptr;
    const __nv_bfloat16* wHi = g_wbf_hi + (size_t)conv_idx * KCONV * 128;
    const __nv_bfloat16* wLo = g_wbf_lo + (size_t)conv_idx * KCONV * 128;

    const int t    = threadIdx.x;
    const int lane = t & 31;
    const int wid  = t >> 5;
    const int warpM = wid >> 2;
    const int warpN = wid & 3;

    const int blk = blockIdx.x;
    const int b   = blk >> 10;
    const int th  = (blk & 1023) >> 5;
    const int tw  = blk & 31;
    const int h0  = th*8, w0 = tw*8;

    for (int idx = t; idx < 3200; idx += 256) {
        int r  = idx >> 5;
        int c4 = idx & 31;
        int hh = h0 + (r/10) - 1;
        int ww = w0 + (r%10) - 1;
        float4 v = make_float4(0.f, 0.f, 0.f, 0.f);
        if (hh >= 0 && hh < IMGH && ww >= 0 && ww < IMGW)
            v = *(const float4*)(in + (((size_t)b*IMGH + hh)*IMGW + ww)*CDIM + c4*4);
        split_store(aHiP, aLoP, r*A_PITCH_E + c4*4, v);
    }

    const int prow = t >> 4;
    const int pseg = t & 15;
    auto prefetchB = [&](int ks, int stage) {
        size_t gofs = ((size_t)(ks*16 + prow))*128 + pseg*8;
        uint32_t d = bU + stage*8704 + prow*A_PITCH_B + pseg*16;
        cp_async16(d,        wHi + gofs);
        cp_async16(d + 4352, wLo + gofs);
    };

    prefetchB(0, 0);
    asm volatile("cp.async.commit_group;");
    __syncthreads();

    float acc[2][4][4];
    #pragma unroll
    for (int mi = 0; mi < 2; mi++)
        #pragma unroll
        for (int ni = 0; ni < 4; ni++)
            #pragma unroll
            for (int e = 0; e < 4; e++) acc[mi][ni][e] = 0.f;

    for (int ks = 0; ks < 72; ks++) {
        const int stage = ks & 1;
        if (ks < 71) {
            prefetchB(ks + 1, stage ^ 1);
            asm volatile("cp.async.commit_group;");
            asm volatile("cp.async.wait_group 1;");
        } else {
            asm volatile("cp.async.wait_group 0;");
        }
        __syncthreads();

        const int tap = ks >> 3;
        const int kc  = (ks & 7) << 4;
        const int dy  = tap / 3;
        const int dx  = tap - dy*3;

        uint32_t a_hi[2][4], a_lo[2][4];
        #pragma unroll
        for (int mi = 0; mi < 2; mi++) {
            int p = warpM*32 + mi*16 + (lane & 15);
            int r = ((p >> 3) + dy)*10 + (p & 7) + dx;
            uint32_t off = (uint32_t)(r*A_PITCH_B + (kc + ((lane >> 4) << 3))*2);
            ldsm4(a_hi[mi], aHiU + off);
            ldsm4(a_lo[mi], aLoU + off);
        }

        uint32_t b_hi[4][2], b_lo[4][2];
        const uint32_t bst = bU + stage*8704;
        #pragma unroll
        for (int pair = 0; pair < 2; pair++) {
            uint32_t off = (uint32_t)((lane & 15)*A_PITCH_B +
                           (warpN*32 + pair*16 + ((lane >> 4) << 3))*2);
            uint32_t r4[4];
            ldsm4t(r4, bst + off);
            b_hi[pair*2][0] = r4[0]; b_hi[pair*2][1] = r4[1];
            b_hi[pair*2+1][0] = r4[2]; b_hi[pair*2+1][1] = r4[3];
            ldsm4t(r4, bst + 4352 + off);
            b_lo[pair*2][0] = r4[0]; b_lo[pair*2][1] = r4[1];
            b_lo[pair*2+1][0] = r4[2]; b_lo[pair*2+1][1] = r4[3];
        }

        #pragma unroll
        for (int mi = 0; mi < 2; mi++)
            #pragma unroll
            for (int ni = 0; ni < 4; ni++) {
                mma16816(acc[mi][ni], a_hi[mi], b_hi[ni]);
                mma16816(acc[mi][ni], a_hi[mi], b_lo[ni]);
                mma16816(acc[mi][ni], a_lo[mi], b_hi[ni]);
            }
        __syncthreads();
    }

    #pragma unroll
    for (int mi = 0; mi < 2; mi++) {
        #pragma unroll
        for (int ni = 0; ni < 4; ni++) {
            int p0 = warpM*32 + mi*16 + (lane >> 2);
            int p1 = p0 + 8;
            int ch = warpN*32 + ni*8 + (lane & 3)*2;
            float2 bb = *(const float2*)(bias + ch);
            float v00 = acc[mi][ni][0] + bb.x, v01 = acc[mi][ni][1] + bb.y;
            float v10 = acc[mi][ni][2] + bb.x, v11 = acc[mi][ni][3] + bb.y;
            if (relu) {
                v00 = fmaxf(v00, 0.f); v01 = fmaxf(v01, 0.f);
                v10 = fmaxf(v10, 0.f); v11 = fmaxf(v11, 0.f);
            }
            size_t g0 = (((size_t)b*IMGH + h0 + (p0 >> 3))*IMGW + w0 + (p0 & 7))*CDIM + ch;
            size_t g1 = (((size_t)b*IMGH + h0 + (p1 >> 3))*IMGW + w0 + (p1 & 7))*CDIM + ch;
            if (res) {
                float2 r0 = *(const float2*)(res + g0);
                float2 r1 = *(const float2*)(res + g1);
                v00 += r0.x; v01 += r0.y; v10 += r1.x; v11 += r1.y;
            }
            *(float2*)(out + g0) = make_float2(v00, v01);
            *(float2*)(out + g1) = make_float2(v10, v11);
        }
    }
}

// ================= proj 1x1 (mma) + window_partition -> d_out =================
#define PROJ_SMEM 52224
__global__ __launch_bounds__(256) void proj_mma(
    const float* __restrict__ proj_b, float* __restrict__ out)
{
    extern __shared__ __align__(16) unsigned char smem_raw[];
    __nv_bfloat16* aHiP = reinterpret_cast<__nv_bfloat16*>(smem_raw);
    __nv_bfloat16* aLoP = aHiP + 64*136;
    const uint32_t smem_u = (uint32_t)__cvta_generic_to_shared(smem_raw);
    const uint32_t aHiU = smem_u, aLoU = smem_u + 17408, bU = smem_u + 34816;

    const int t = threadIdx.x, lane = t & 31, wid = t >> 5;
    const int warpM = wid >> 2, warpN = wid & 3;
    const int win = blockIdx.x;
    const int b   = win >> 10;
    const int hw  = (win & 1023) >> 5;
    const int ww  = win & 31;
    const float* img = g_imgA;

    for (int idx = t; idx < 2048; idx += 256) {
        int tok = idx >> 5, c4 = idx & 31;
        int i1 = tok >> 3, j1 = tok & 7;
        size_t pix = (((size_t)b*IMGH + hw*8 + i1)*IMGW + (ww*8 + j1))*CDIM;
        float4 v = *(const float4*)(img + pix + c4*4);
        split_store(aHiP, aLoP, tok*136 + c4*4, v);
    }

    auto prefetchB = [&](int ks, int stage) {
        #pragma unroll
        for (int i = 0; i < 2; i++) {
            int c = t + i*256;
            int part = c >= 256; int cc = c - part*256;
            int row = cc >> 4, seg = cc & 15;
            const __nv_bfloat16* sp = (part ? g_wproj_lo : g_wproj_hi) + (ks*16 + row)*128 + seg*8;
            cp_async16(bU + stage*8704 + part*4352 + row*272 + seg*16, sp);
        }
    };
    prefetchB(0, 0);
    asm volatile("cp.async.commit_group;");
    __syncthreads();

    float acc[2][4][4];
    #pragma unroll
    for (int mi = 0; mi < 2; mi++)
        #pragma unroll
        for (int ni = 0; ni < 4; ni++)
            #pragma unroll
            for (int e = 0; e < 4; e++) acc[mi][ni][e] = 0.f;

    for (int ks = 0; ks < 8; ks++) {
        const int stage = ks & 1;
        if (ks < 7) {
            prefetchB(ks + 1, stage ^ 1);
            asm volatile("cp.async.commit_group;");
            asm volatile("cp.async.wait_group 1;");
        } else {
            asm volatile("cp.async.wait_group 0;");
        }
        __syncthreads();

        const int kc = ks * 16;
        uint32_t a_hi[2][4], a_lo[2][4];
        #pragma unroll
        for (int mi = 0; mi < 2; mi++) {
            int row = warpM*32 + mi*16 + (lane & 15);
            uint32_t off = (uint32_t)(row*272 + (kc + ((lane >> 4) << 3))*2);
            ldsm4(a_hi[mi], aHiU + off);
            ldsm4(a_lo[mi], aLoU + off);
        }
        const uint32_t bst = bU + stage*8704;
        #pragma unroll
        for (int pair = 0; pair < 2; pair++) {
            uint32_t off = (uint32_t)((lane & 15)*272 +
                           (warpN*32 + pair*16 + ((lane >> 4) << 3))*2);
            uint32_t bh[4], bl[4];
            ldsm4t(bh, bst + off);
            ldsm4t(bl, bst + 4352 + off);
            #pragma unroll
            for (int mi = 0; mi < 2; mi++) {
                mma16816(acc[mi][2*pair],   a_hi[mi], bh);
                mma16816(acc[mi][2*pair],   a_hi[mi], bl);
                mma16816(acc[mi][2*pair],   a_lo[mi], bh);
                mma16816(acc[mi][2*pair+1], a_hi[mi], bh+2);
                mma16816(acc[mi][2*pair+1], a_hi[mi], bl+2);
                mma16816(acc[mi][2*pair+1], a_lo[mi], bh+2);
            }
        }
        __syncthreads();
    }

    float* outw = out + (size_t)win * NTOK * CDIM;
    #pragma unroll
    for (int mi = 0; mi < 2; mi++) {
        int row0 = warpM*32 + mi*16 + (lane >> 2);
        int row1 = row0 + 8;
        #pragma unroll
        for (int ni = 0; ni < 4; ni++) {
            int ch = warpN*32 + ni*8 + (lane & 3)*2;
            float2 bb = *(const float2*)(proj_b + ch);
            *(float2*)(outw + row0*128 + ch) =
                make_float2(acc[mi][ni][0] + bb.x, acc[mi][ni][1] + bb.y);
            *(float2*)(outw + row1*128 + ch) =
                make_float2(acc[mi][ni][2] + bb.x, acc[mi][ni][3] + bb.y);
        }
    }
}

// ---------------- launch ----------------
extern "C" void kernel_launch(void* const* d_in, const int* in_sizes, int n_in,
                              void* d_out, int out_size) {
    const float* x         = (const float*)d_in[0];
    const float* ref       = (const float*)d_in[1];
    const float* qkv_w     = (const float*)d_in[2];
    const float* qkv_b     = (const float*)d_in[3];
    const float* proj_w    = (const float*)d_in[4];
    const float* proj_b    = (const float*)d_in[5];
    const float* t11w      = (const float*)d_in[6];
    const float* t11b      = (const float*)d_in[7];
    const float* t12w      = (const float*)d_in[8];
    const float* t12b      = (const float*)d_in[9];
    const float* t21w      = (const float*)d_in[10];
    const float* t21b      = (const float*)d_in[11];
    const float* t22w      = (const float*)d_in[12];
    const float* t22b      = (const float*)d_in[13];
    const float* rel_bias  = (const float*)d_in[14];
    const float* logit_sc  = (const float*)d_in[15];
    const float* gating    = (const float*)d_in[16];
    float* out = (float*)d_out;

    cudaFuncSetAttribute(attn_kernel, cudaFuncAttributeMaxDynamicSharedMemorySize,
                         ATTN_SMEM_FLOATS * (int)sizeof(float));
    cudaFuncSetAttribute(conv3x3_mma, cudaFuncAttributeMaxDynamicSharedMemorySize,
                         CONV_SMEM_BYTES);
    cudaFuncSetAttribute(qkv_mma,  cudaFuncAttributeMaxDynamicSharedMemorySize, QKV_SMEM);
    cudaFuncSetAttribute(kref_mma, cudaFuncAttributeMaxDynamicSharedMemorySize, KREF_SMEM);
    cudaFuncSetAttribute(proj_mma, cudaFuncAttributeMaxDynamicSharedMemorySize, PROJ_SMEM);

    prep_weights<<<192, 256>>>(qkv_w, proj_w);
    split_weights<<<(KCONV*128 + 255)/256, 256>>>(t11w, t12w, t21w, t22w);

    qkv_mma<<<NWIN, 256, QKV_SMEM>>>(x, qkv_b);
    kref_mma<<<NWIN, 256, KREF_SMEM>>>(ref, qkv_b);

    attn_kernel<<<NWIN, 256, ATTN_SMEM_FLOATS * (int)sizeof(float)>>>(rel_bias, logit_sc, gating);

    conv3x3_mma<<<NWIN, 256, CONV_SMEM_BYTES>>>(0, 0, t11b, -1, 1, 1);
    conv3x3_mma<<<NWIN, 256, CONV_SMEM_BYTES>>>(1, 1, t12b,  0, 2, 0);
    conv3x3_mma<<<NWIN, 256, CONV_SMEM_BYTES>>>(2, 2, t21b, -1, 1, 1);
    conv3x3_mma<<<NWIN, 256, CONV_SMEM_BYTES>>>(1, 3, t22b,  2, 0, 0);

    proj_mma<<<NWIN, 256, PROJ_SMEM>>>(proj_b, out);
}